// round 9
// baseline (speedup 1.0000x reference)
#include <cuda_runtime.h>
#include <cuda_bf16.h>
#include <stdint.h>
#include <math.h>

#define SEQ 4096
#define DIM 768
#define NH  12
#define HD  64
#define NL  12
#define FFD 3072
#define WIN 256
#define EPSF 1e-5f

// ---------------- scratch (static device globals; no runtime allocation) ----
__device__ float g_x[SEQ * DIM];
__device__ float g_qkv[SEQ * 3 * DIM];
__device__ float g_t[SEQ * DIM];
__device__ float g_bcat[NL * 3 * DIM];
__device__ int   g_pos[SEQ];

__device__ __nv_bfloat16 g_xh[SEQ * DIM],  g_xl[SEQ * DIM];
__device__ __nv_bfloat16 g_ah[SEQ * DIM],  g_al[SEQ * DIM];
__device__ __nv_bfloat16 g_hh[SEQ * FFD],  g_hl[SEQ * FFD];
// per-layer split weights (hoisted: all layers prepared upfront)
__device__ __nv_bfloat16 g_wqh[(size_t)NL * DIM * 3 * DIM], g_wql[(size_t)NL * DIM * 3 * DIM];
__device__ __nv_bfloat16 g_w1h[(size_t)NL * DIM * FFD], g_w1l[(size_t)NL * DIM * FFD];
__device__ __nv_bfloat16 g_w2h[(size_t)NL * FFD * DIM], g_w2l[(size_t)NL * FFD * DIM];
__device__ __nv_bfloat16 g_woh[(size_t)NL * DIM * DIM], g_wol[(size_t)NL * DIM * DIM];

// ---------------- helpers ---------------------------------------------------
__device__ __forceinline__ float gelu_exact(float x) {
    return 0.5f * x * (1.0f + erff(x * 0.70710678118654752f));
}

__device__ __forceinline__ uint32_t pack_bf16x2(float x, float y) {
    __nv_bfloat162 h = __floats2bfloat162_rn(x, y);
    return *(uint32_t*)&h;
}

__device__ __forceinline__ void mma_bf16(float& d0, float& d1, float& d2, float& d3,
                                         uint32_t a0, uint32_t a1, uint32_t a2, uint32_t a3,
                                         uint32_t b0, uint32_t b1) {
    asm volatile("mma.sync.aligned.m16n8k16.row.col.f32.bf16.bf16.f32 "
                 "{%0,%1,%2,%3}, {%4,%5,%6,%7}, {%8,%9}, {%0,%1,%2,%3};"
                 : "+f"(d0), "+f"(d1), "+f"(d2), "+f"(d3)
                 : "r"(a0), "r"(a1), "r"(a2), "r"(a3), "r"(b0), "r"(b1));
}

__device__ __forceinline__ void ldsm4(uint32_t& r0, uint32_t& r1, uint32_t& r2, uint32_t& r3,
                                      uint32_t addr) {
    asm volatile("ldmatrix.sync.aligned.m8n8.x4.shared.b16 {%0,%1,%2,%3}, [%4];"
                 : "=r"(r0), "=r"(r1), "=r"(r2), "=r"(r3) : "r"(addr));
}

__device__ __forceinline__ void ldsm4t(uint32_t& r0, uint32_t& r1, uint32_t& r2, uint32_t& r3,
                                       uint32_t addr) {
    asm volatile("ldmatrix.sync.aligned.m8n8.x4.trans.shared.b16 {%0,%1,%2,%3}, [%4];"
                 : "=r"(r0), "=r"(r1), "=r"(r2), "=r"(r3) : "r"(addr));
}

__device__ __forceinline__ void cp16(uint32_t saddr, const void* gaddr) {
    asm volatile("cp.async.cg.shared.global [%0], [%1], 16;" :: "r"(saddr), "l"(gaddr));
}

__device__ __forceinline__ void split_store8(char* hp, char* lp, float4 v) {
    __nv_bfloat162 h01 = __floats2bfloat162_rn(v.x, v.y);
    __nv_bfloat162 h23 = __floats2bfloat162_rn(v.z, v.w);
    uint2 hh;
    hh.x = *(uint32_t*)&h01;
    hh.y = *(uint32_t*)&h23;
    uint2 ll;
    ll.x = pack_bf16x2(v.x - __bfloat162float(h01.x), v.y - __bfloat162float(h01.y));
    ll.y = pack_bf16x2(v.z - __bfloat162float(h23.x), v.w - __bfloat162float(h23.y));
    *(uint2*)hp = hh;
    *(uint2*)lp = ll;
}

__device__ __forceinline__ float blk_sum256(float v, float* red) {
    #pragma unroll
    for (int o = 16; o > 0; o >>= 1) v += __shfl_down_sync(0xffffffffu, v, o);
    int w = threadIdx.x >> 5;
    if ((threadIdx.x & 31) == 0) red[w] = v;
    __syncthreads();
    if (threadIdx.x < 32) {
        v = (threadIdx.x < 8) ? red[threadIdx.x] : 0.0f;
        #pragma unroll
        for (int o = 4; o > 0; o >>= 1) v += __shfl_down_sync(0xffffffffu, v, o);
        if (threadIdx.x == 0) red[0] = v;
    }
    __syncthreads();
    float r = red[0];
    __syncthreads();
    return r;
}

// ---------------- pos_ids = cumsum(mask)*mask + 1 ---------------------------
__global__ void pos_kernel(const int* __restrict__ mask, int* __restrict__ pos) {
    __shared__ int ss[1024];
    int t = threadIdx.x;
    int m0 = mask[t * 4 + 0], m1 = mask[t * 4 + 1];
    int m2 = mask[t * 4 + 2], m3 = mask[t * 4 + 3];
    int s = m0 + m1 + m2 + m3;
    ss[t] = s;
    __syncthreads();
    for (int off = 1; off < 1024; off <<= 1) {
        int vprev = (t >= off) ? ss[t - off] : 0;
        __syncthreads();
        ss[t] += vprev;
        __syncthreads();
    }
    int run = ss[t] - s;
    run += m0; pos[t * 4 + 0] = run * m0 + 1;
    run += m1; pos[t * 4 + 1] = run * m1 + 1;
    run += m2; pos[t * 4 + 2] = run * m2 + 1;
    run += m3; pos[t * 4 + 3] = run * m3 + 1;
}

// ---------------- embedding + layernorm (writes f32 + bf16 hi/lo) -----------
__global__ void embed_ln_kernel(const int* __restrict__ ids, const int* __restrict__ pos,
                                const float* __restrict__ ew, const float* __restrict__ ep,
                                const float* __restrict__ et, const float* __restrict__ g,
                                const float* __restrict__ b, float* __restrict__ x,
                                __nv_bfloat16* __restrict__ xh, __nv_bfloat16* __restrict__ xl) {
    __shared__ float red[32];
    int srow = blockIdx.x;
    int t = threadIdx.x;
    int wid = ids[srow];
    int pid = pos[srow];
    float val[3];
    #pragma unroll
    for (int r = 0; r < 3; r++) {
        int i = t + r * 256;
        val[r] = ew[(size_t)wid * DIM + i] + ep[(size_t)pid * DIM + i] + et[i];
    }
    float mu = blk_sum256(val[0] + val[1] + val[2], red) * (1.0f / DIM);
    float vs = 0.0f;
    #pragma unroll
    for (int r = 0; r < 3; r++) { float d = val[r] - mu; vs += d * d; }
    float var = blk_sum256(vs, red) * (1.0f / DIM);
    float rs = rsqrtf(var + EPSF);
    #pragma unroll
    for (int r = 0; r < 3; r++) {
        int i = t + r * 256;
        float y = (val[r] - mu) * rs * g[i] + b[i];
        size_t idx = (size_t)srow * DIM + i;
        x[idx] = y;
        __nv_bfloat16 h = __float2bfloat16_rn(y);
        xh[idx] = h;
        xl[idx] = __float2bfloat16_rn(y - __bfloat162float(h));
    }
}

// ---------------- x = LN(x + delta), writes f32 + bf16 hi/lo -----------------
__global__ void lnres_kernel(float* __restrict__ x, const float* __restrict__ delta,
                             const float* __restrict__ g, const float* __restrict__ b,
                             __nv_bfloat16* __restrict__ xh, __nv_bfloat16* __restrict__ xl) {
    __shared__ float red[32];
    int srow = blockIdx.x;
    int t = threadIdx.x;
    float val[3];
    #pragma unroll
    for (int r = 0; r < 3; r++) {
        int i = t + r * 256;
        val[r] = x[(size_t)srow * DIM + i] + delta[(size_t)srow * DIM + i];
    }
    float mu = blk_sum256(val[0] + val[1] + val[2], red) * (1.0f / DIM);
    float vs = 0.0f;
    #pragma unroll
    for (int r = 0; r < 3; r++) { float d = val[r] - mu; vs += d * d; }
    float var = blk_sum256(vs, red) * (1.0f / DIM);
    float rs = rsqrtf(var + EPSF);
    #pragma unroll
    for (int r = 0; r < 3; r++) {
        int i = t + r * 256;
        float y = (val[r] - mu) * rs * g[i] + b[i];
        size_t idx = (size_t)srow * DIM + i;
        x[idx] = y;
        __nv_bfloat16 h = __float2bfloat16_rn(y);
        xh[idx] = h;
        xl[idx] = __float2bfloat16_rn(y - __bfloat162float(h));
    }
}

// ---------------- generic f32 -> bf16 hi/lo split -----------------------------
__global__ void split_kernel(const float* __restrict__ s, __nv_bfloat16* __restrict__ hi,
                             __nv_bfloat16* __restrict__ lo, int n4) {
    int i = blockIdx.x * blockDim.x + threadIdx.x;
    if (i >= n4) return;
    float4 v = ((const float4*)s)[i];
    __nv_bfloat16 h0 = __float2bfloat16_rn(v.x), h1 = __float2bfloat16_rn(v.y);
    __nv_bfloat16 h2 = __float2bfloat16_rn(v.z), h3 = __float2bfloat16_rn(v.w);
    uint2 hp, lp;
    hp.x = ((uint32_t)*(uint16_t*)&h0) | ((uint32_t)*(uint16_t*)&h1 << 16);
    hp.y = ((uint32_t)*(uint16_t*)&h2) | ((uint32_t)*(uint16_t*)&h3 << 16);
    lp.x = pack_bf16x2(v.x - __bfloat162float(h0), v.y - __bfloat162float(h1));
    lp.y = pack_bf16x2(v.z - __bfloat162float(h2), v.w - __bfloat162float(h3));
    ((uint2*)hi)[i] = hp;
    ((uint2*)lo)[i] = lp;
}

// ---------------- concat QKV weights (split to bf16) + bias ------------------
__global__ void concat_qkv_kernel(const float* __restrict__ Wq, const float* __restrict__ Wk,
                                  const float* __restrict__ Wv, const float* __restrict__ bq,
                                  const float* __restrict__ bk, const float* __restrict__ bv,
                                  __nv_bfloat16* __restrict__ Wh, __nv_bfloat16* __restrict__ Wl,
                                  float* __restrict__ bc) {
    int i4 = blockIdx.x * blockDim.x + threadIdx.x;
    if (i4 < DIM * DIM / 4) {
        int k = i4 / (DIM / 4);
        int n4 = i4 % (DIM / 4);
        const float* srcs[3] = {Wq, Wk, Wv};
        #pragma unroll
        for (int s = 0; s < 3; s++) {
            float4 v = ((const float4*)srcs[s])[i4];
            __nv_bfloat16 h0 = __float2bfloat16_rn(v.x), h1 = __float2bfloat16_rn(v.y);
            __nv_bfloat16 h2 = __float2bfloat16_rn(v.z), h3 = __float2bfloat16_rn(v.w);
            uint2 hp, lp;
            hp.x = ((uint32_t)*(uint16_t*)&h0) | ((uint32_t)*(uint16_t*)&h1 << 16);
            hp.y = ((uint32_t)*(uint16_t*)&h2) | ((uint32_t)*(uint16_t*)&h3 << 16);
            lp.x = pack_bf16x2(v.x - __bfloat162float(h0), v.y - __bfloat162float(h1));
            lp.y = pack_bf16x2(v.z - __bfloat162float(h2), v.w - __bfloat162float(h3));
            int e = k * 3 * DIM + s * DIM + n4 * 4;
            ((uint2*)Wh)[e >> 2] = hp;
            ((uint2*)Wl)[e >> 2] = lp;
        }
    }
    if (i4 < DIM / 4) {
        ((float4*)bc)[i4] = ((const float4*)bq)[i4];
        ((float4*)(bc + DIM))[i4] = ((const float4*)bk)[i4];
        ((float4*)(bc + 2 * DIM))[i4] = ((const float4*)bv)[i4];
    }
}

// ---------------- bf16x3 tensor-core GEMM (cp.async + ldmatrix) --------------
// C[M,N] = A[M,K] @ B[K,N] + bias. A,B pre-split into bf16 hi/lo in gmem.
// acc = hiA*hiB + hiA*loB + loA*hiB (3 MMAs, fp32-comparable accuracy).
// BN=128, 256 threads (8 warps), k16 stages, 2-stage cp.async pipeline.
// A smem: [BM] rows, 48B pitch (32B data) -> ldmatrix banks (r*12)%32, conflict-free.
// B smem: [16][128] bf16 k-major, XOR-swizzled 16B chunks -> ldmatrix.x4.trans.
template <int BM, int OUT>
__global__ __launch_bounds__(256) void tgemm_kernel(
    const __nv_bfloat16* __restrict__ Ah, const __nv_bfloat16* __restrict__ Al,
    const __nv_bfloat16* __restrict__ Bh, const __nv_bfloat16* __restrict__ Bl,
    const float* __restrict__ bias, float* __restrict__ C,
    __nv_bfloat16* __restrict__ Chi, __nv_bfloat16* __restrict__ Clo,
    int M, int N, int K) {
    constexpr int MT = BM / 64;
    constexpr int PA = 48;                 // A row pitch (bytes)
    constexpr int OFF_AH = 0;
    constexpr int OFF_AL = BM * PA;
    constexpr int OFF_BH = 2 * BM * PA;
    constexpr int OFF_BL = 2 * BM * PA + 4096;
    constexpr int STAGE  = 2 * BM * PA + 8192;

    __shared__ __align__(16) unsigned char smem_raw[2 * STAGE];
    uint32_t smemb = (uint32_t)__cvta_generic_to_shared(smem_raw);

    const int bx = blockIdx.x;
    const int by = blockIdx.y;
    const int tid = threadIdx.x;
    const int lane = tid & 31;
    const int wid = tid >> 5;
    const int warpM = wid & 3;
    const int warpN = wid >> 2;
    const int gid = lane >> 2;
    const int tig = lane & 3;
    const int mBase = warpM * 16 * MT;
    const int nBase = warpN * 64;
    const int rowbase = by * BM;
    const int colbase = bx * 128;

    float acc[MT][8][4];
    #pragma unroll
    for (int mt = 0; mt < MT; mt++)
        #pragma unroll
        for (int nt = 0; nt < 8; nt++)
            #pragma unroll
            for (int r = 0; r < 4; r++) acc[mt][nt][r] = 0.0f;

    const int am = tid >> 1;
    const int ah = tid & 1;
    const int bkrow = tid >> 4;
    const int bch = tid & 15;
    const int bchs = bch ^ (bkrow & 7);

    auto issue = [&](int st, int k0) {
        uint32_t sb = smemb + st * STAGE;
        if (BM == 128 || tid < 128) {
            size_t go = (size_t)(rowbase + am) * K + k0 + ah * 8;
            uint32_t so = (uint32_t)(am * PA + ah * 16);
            cp16(sb + OFF_AH + so, Ah + go);
            cp16(sb + OFF_AL + so, Al + go);
        }
        {
            size_t go = (size_t)(k0 + bkrow) * N + colbase + bch * 8;
            uint32_t so = (uint32_t)(bkrow * 256 + bchs * 16);
            cp16(sb + OFF_BH + so, Bh + go);
            cp16(sb + OFF_BL + so, Bl + go);
        }
    };

    const int KT = K >> 4;
    issue(0, 0);
    asm volatile("cp.async.commit_group;" ::: "memory");

    const int lane15 = lane & 15;
    const int laneh = lane >> 4;
    const int bk = lane & 15;
    const int bs = (lane >> 4) & 1;

    for (int t = 0; t < KT; t++) {
        if (t + 1 < KT) {
            issue((t + 1) & 1, (t + 1) * 16);
            asm volatile("cp.async.commit_group;" ::: "memory");
            asm volatile("cp.async.wait_group 1;" ::: "memory");
        } else {
            asm volatile("cp.async.wait_group 0;" ::: "memory");
        }
        __syncthreads();

        uint32_t sb = smemb + (t & 1) * STAGE;
        uint32_t aAddr = sb + OFF_AH + (uint32_t)((mBase + lane15) * PA + laneh * 16);
        uint32_t aHi[MT][4], aLo[MT][4];
        #pragma unroll
        for (int mt = 0; mt < MT; mt++) {
            ldsm4(aHi[mt][0], aHi[mt][1], aHi[mt][2], aHi[mt][3], aAddr + mt * 16 * PA);
            ldsm4(aLo[mt][0], aLo[mt][1], aLo[mt][2], aLo[mt][3],
                  aAddr + (OFF_AL - OFF_AH) + mt * 16 * PA);
        }
        uint32_t bRow = sb + OFF_BH + (uint32_t)(bk * 256);
        #pragma unroll
        for (int nt2 = 0; nt2 < 4; nt2++) {
            uint32_t ch = (uint32_t)((((warpN * 8 + nt2 * 2 + bs) ^ (bk & 7))) * 16);
            uint32_t bh0, bh1, bh2, bh3, bl0, bl1, bl2, bl3;
            ldsm4t(bh0, bh1, bh2, bh3, bRow + ch);
            ldsm4t(bl0, bl1, bl2, bl3, bRow + (OFF_BL - OFF_BH) + ch);
            #pragma unroll
            for (int mt = 0; mt < MT; mt++) {
                float* a0 = acc[mt][nt2 * 2];
                mma_bf16(a0[0], a0[1], a0[2], a0[3],
                         aHi[mt][0], aHi[mt][1], aHi[mt][2], aHi[mt][3], bh0, bh1);
                mma_bf16(a0[0], a0[1], a0[2], a0[3],
                         aHi[mt][0], aHi[mt][1], aHi[mt][2], aHi[mt][3], bl0, bl1);
                mma_bf16(a0[0], a0[1], a0[2], a0[3],
                         aLo[mt][0], aLo[mt][1], aLo[mt][2], aLo[mt][3], bh0, bh1);
                float* a1 = acc[mt][nt2 * 2 + 1];
                mma_bf16(a1[0], a1[1], a1[2], a1[3],
                         aHi[mt][0], aHi[mt][1], aHi[mt][2], aHi[mt][3], bh2, bh3);
                mma_bf16(a1[0], a1[1], a1[2], a1[3],
                         aHi[mt][0], aHi[mt][1], aHi[mt][2], aHi[mt][3], bl2, bl3);
                mma_bf16(a1[0], a1[1], a1[2], a1[3],
                         aLo[mt][0], aLo[mt][1], aLo[mt][2], aLo[mt][3], bh2, bh3);
            }
        }
        __syncthreads();
    }

    #pragma unroll
    for (int nt = 0; nt < 8; nt++) {
        int col = colbase + nBase + nt * 8 + tig * 2;
        float b0 = bias[col], b1 = bias[col + 1];
        #pragma unroll
        for (int mt = 0; mt < MT; mt++) {
            int row0 = rowbase + mBase + mt * 16 + gid;
            float v0 = acc[mt][nt][0] + b0;
            float v1 = acc[mt][nt][1] + b1;
            float v2 = acc[mt][nt][2] + b0;
            float v3 = acc[mt][nt][3] + b1;
            if (OUT == 0) {
                *(float2*)(C + (size_t)row0 * N + col) = make_float2(v0, v1);
                *(float2*)(C + (size_t)(row0 + 8) * N + col) = make_float2(v2, v3);
            } else {
                v0 = gelu_exact(v0); v1 = gelu_exact(v1);
                v2 = gelu_exact(v2); v3 = gelu_exact(v3);
                size_t i0 = ((size_t)row0 * N + col) >> 1;
                size_t i1 = ((size_t)(row0 + 8) * N + col) >> 1;
                __nv_bfloat16 h0 = __float2bfloat16_rn(v0), h1 = __float2bfloat16_rn(v1);
                __nv_bfloat16 h2 = __float2bfloat16_rn(v2), h3 = __float2bfloat16_rn(v3);
                ((uint32_t*)Chi)[i0] = ((uint32_t)*(uint16_t*)&h0) | ((uint32_t)*(uint16_t*)&h1 << 16);
                ((uint32_t*)Chi)[i1] = ((uint32_t)*(uint16_t*)&h2) | ((uint32_t)*(uint16_t*)&h3 << 16);
                ((uint32_t*)Clo)[i0] = pack_bf16x2(v0 - __bfloat162float(h0), v1 - __bfloat162float(h1));
                ((uint32_t*)Clo)[i1] = pack_bf16x2(v2 - __bfloat162float(h2), v3 - __bfloat162float(h3));
            }
        }
    }
}

// ---------------- tensor-core sliding-window flash attention -----------------
#define ATT_SMEM (49152 + 128)
__global__ __launch_bounds__(128) void attn_mma_kernel(
    const float* __restrict__ qkv, const int* __restrict__ mask,
    __nv_bfloat16* __restrict__ oh, __nv_bfloat16* __restrict__ ol) {
    extern __shared__ __align__(16) unsigned char asmem[];
    char* gp = (char*)asmem;
    const uint32_t sb = (uint32_t)__cvta_generic_to_shared(asmem);
    const uint32_t QH = sb, QL = sb + 16384;
    const uint32_t KH = sb + 32768, KL = KH + 4096, VH = KL + 4096, VL = VH + 4096;
    char* gQH = gp; char* gQL = gp + 16384;
    char* gKH = gp + 32768; char* gKL = gKH + 4096;
    char* gVH = gKL + 4096; char* gVL = gVH + 4096;
    int* msk = (int*)(gp + 49152);

    const int h = blockIdx.y;
    const int q0 = blockIdx.x * 128;
    const int tid = threadIdx.x, lane = tid & 31, wid = tid >> 5;
    const int gid = lane >> 2, tig = lane & 3;
    const int mBase = wid * 32;
    const int STR = 3 * DIM;

    #pragma unroll
    for (int i = 0; i < 16; i++) {
        int f = tid + i * 128;
        int row = f >> 4, col4 = f & 15;
        float4 q4 = *(const float4*)(qkv + (size_t)(q0 + row) * STR + h * 64 + col4 * 4);
        q4.x *= 0.125f; q4.y *= 0.125f; q4.z *= 0.125f; q4.w *= 0.125f;
        int chunk = col4 >> 1, half = col4 & 1;
        int off = row * 128 + ((chunk ^ (row & 7)) << 4) + half * 8;
        split_store8(gQH + off, gQL + off, q4);
    }
    __syncthreads();

    uint32_t Qhi[2][4][4], Qlo[2][4][4];
    {
        int arow = (lane & 7) + 8 * ((lane >> 3) & 1);
        int achsel = lane >> 4;
        #pragma unroll
        for (int mt = 0; mt < 2; mt++) {
            int row = mBase + mt * 16 + arow;
            #pragma unroll
            for (int kk = 0; kk < 4; kk++) {
                int chunk = kk * 2 + achsel;
                uint32_t ad = (uint32_t)(row * 128 + ((chunk ^ (row & 7)) << 4));
                ldsm4(Qhi[mt][kk][0], Qhi[mt][kk][1], Qhi[mt][kk][2], Qhi[mt][kk][3], QH + ad);
                ldsm4(Qlo[mt][kk][0], Qlo[mt][kk][1], Qlo[mt][kk][2], Qlo[mt][kk][3], QL + ad);
            }
        }
    }

    float O[2][8][4];
    #pragma unroll
    for (int mt = 0; mt < 2; mt++)
        #pragma unroll
        for (int dj = 0; dj < 8; dj++)
            #pragma unroll
            for (int r = 0; r < 4; r++) O[mt][dj][r] = 0.0f;
    float mrow[2][2] = {{-1e30f, -1e30f}, {-1e30f, -1e30f}};
    float lrow[2][2] = {{0.0f, 0.0f}, {0.0f, 0.0f}};

    const int warpLo = q0 + mBase - WIN;
    const int warpHi = q0 + mBase + 31 + WIN;

    for (int c = q0 - WIN; c < q0 + 128 + WIN; c += 32) {
        #pragma unroll
        for (int i = 0; i < 4; i++) {
            int f = tid + i * 128;
            int row = f >> 4, col4 = f & 15;
            int kp = c + row;
            int kc = kp < 0 ? 0 : (kp >= SEQ ? SEQ - 1 : kp);
            float4 kv = *(const float4*)(qkv + (size_t)kc * STR + DIM + h * 64 + col4 * 4);
            float4 vv = *(const float4*)(qkv + (size_t)kc * STR + 2 * DIM + h * 64 + col4 * 4);
            int chunk = col4 >> 1, half = col4 & 1;
            int off = row * 128 + ((chunk ^ (row & 7)) << 4) + half * 8;
            split_store8(gKH + off, gKL + off, kv);
            split_store8(gVH + off, gVL + off, vv);
        }
        if (tid < 32) {
            int kp = c + tid;
            msk[tid] = (kp >= 0 && kp < SEQ) ? mask[kp] : 0;
        }
        __syncthreads();

        if (c + 31 >= warpLo && c <= warpHi) {
            float S[2][4][4];
            #pragma unroll
            for (int mt = 0; mt < 2; mt++)
                #pragma unroll
                for (int j = 0; j < 4; j++)
                    #pragma unroll
                    for (int r = 0; r < 4; r++) S[mt][j][r] = 0.0f;

            #pragma unroll
            for (int j = 0; j < 4; j++) {
                uint32_t kh[4][2], kl[4][2];
                int krow = j * 8 + (lane & 7);
                #pragma unroll
                for (int h32 = 0; h32 < 2; h32++) {
                    int chunk = h32 * 4 + (lane >> 3);
                    uint32_t ad = (uint32_t)(krow * 128 + ((chunk ^ (krow & 7)) << 4));
                    uint32_t r0, r1, r2, r3;
                    ldsm4(r0, r1, r2, r3, KH + ad);
                    kh[h32 * 2][0] = r0; kh[h32 * 2][1] = r1;
                    kh[h32 * 2 + 1][0] = r2; kh[h32 * 2 + 1][1] = r3;
                    ldsm4(r0, r1, r2, r3, KL + ad);
                    kl[h32 * 2][0] = r0; kl[h32 * 2][1] = r1;
                    kl[h32 * 2 + 1][0] = r2; kl[h32 * 2 + 1][1] = r3;
                }
                #pragma unroll
                for (int kk = 0; kk < 4; kk++)
                    #pragma unroll
                    for (int mt = 0; mt < 2; mt++) {
                        float* s = S[mt][j];
                        mma_bf16(s[0], s[1], s[2], s[3],
                                 Qhi[mt][kk][0], Qhi[mt][kk][1], Qhi[mt][kk][2], Qhi[mt][kk][3],
                                 kh[kk][0], kh[kk][1]);
                        mma_bf16(s[0], s[1], s[2], s[3],
                                 Qhi[mt][kk][0], Qhi[mt][kk][1], Qhi[mt][kk][2], Qhi[mt][kk][3],
                                 kl[kk][0], kl[kk][1]);
                        mma_bf16(s[0], s[1], s[2], s[3],
                                 Qlo[mt][kk][0], Qlo[mt][kk][1], Qlo[mt][kk][2], Qlo[mt][kk][3],
                                 kh[kk][0], kh[kk][1]);
                    }
            }

            float p[2][4][4];
            #pragma unroll
            for (int mt = 0; mt < 2; mt++) {
                int rA = q0 + mBase + mt * 16 + gid;
                int rB = rA + 8;
                float mxA = -1e30f, mxB = -1e30f;
                #pragma unroll
                for (int j = 0; j < 4; j++) {
                    int c0 = c + j * 8 + tig * 2;
                    int c1 = c0 + 1;
                    int mk0 = msk[j * 8 + tig * 2];
                    int mk1 = msk[j * 8 + tig * 2 + 1];
                    bool v00 = mk0 && (c0 >= rA - WIN) && (c0 <= rA + WIN);
                    bool v01 = mk1 && (c1 >= rA - WIN) && (c1 <= rA + WIN);
                    bool v10 = mk0 && (c0 >= rB - WIN) && (c0 <= rB + WIN);
                    bool v11 = mk1 && (c1 >= rB - WIN) && (c1 <= rB + WIN);
                    S[mt][j][0] = v00 ? S[mt][j][0] : -1e30f;
                    S[mt][j][1] = v01 ? S[mt][j][1] : -1e30f;
                    S[mt][j][2] = v10 ? S[mt][j][2] : -1e30f;
                    S[mt][j][3] = v11 ? S[mt][j][3] : -1e30f;
                    mxA = fmaxf(mxA, fmaxf(S[mt][j][0], S[mt][j][1]));
                    mxB = fmaxf(mxB, fmaxf(S[mt][j][2], S[mt][j][3]));
                }
                mxA = fmaxf(mxA, __shfl_xor_sync(0xffffffffu, mxA, 1));
                mxA = fmaxf(mxA, __shfl_xor_sync(0xffffffffu, mxA, 2));
                mxB = fmaxf(mxB, __shfl_xor_sync(0xffffffffu, mxB, 1));
                mxB = fmaxf(mxB, __shfl_xor_sync(0xffffffffu, mxB, 2));
                float mnA = fmaxf(mrow[mt][0], mxA);
                float mnB = fmaxf(mrow[mt][1], mxB);
                float scA = __expf(mrow[mt][0] - mnA);
                float scB = __expf(mrow[mt][1] - mnB);
                mrow[mt][0] = mnA; mrow[mt][1] = mnB;
                float sA = 0.0f, sB = 0.0f;
                #pragma unroll
                for (int j = 0; j < 4; j++) {
                    float p0 = (S[mt][j][0] > -1e29f) ? __expf(S[mt][j][0] - mnA) : 0.0f;
                    float p1 = (S[mt][j][1] > -1e29f) ? __expf(S[mt][j][1] - mnA) : 0.0f;
                    float p2 = (S[mt][j][2] > -1e29f) ? __expf(S[mt][j][2] - mnB) : 0.0f;
                    float p3 = (S[mt][j][3] > -1e29f) ? __expf(S[mt][j][3] - mnB) : 0.0f;
                    p[mt][j][0] = p0; p[mt][j][1] = p1; p[mt][j][2] = p2; p[mt][j][3] = p3;
                    sA += p0 + p1; sB += p2 + p3;
                }
                sA += __shfl_xor_sync(0xffffffffu, sA, 1);
                sA += __shfl_xor_sync(0xffffffffu, sA, 2);
                sB += __shfl_xor_sync(0xffffffffu, sB, 1);
                sB += __shfl_xor_sync(0xffffffffu, sB, 2);
                lrow[mt][0] = lrow[mt][0] * scA + sA;
                lrow[mt][1] = lrow[mt][1] * scB + sB;
                #pragma unroll
                for (int dj = 0; dj < 8; dj++) {
                    O[mt][dj][0] *= scA; O[mt][dj][1] *= scA;
                    O[mt][dj][2] *= scB; O[mt][dj][3] *= scB;
                }
            }

            uint32_t Phi[2][2][4], Plo[2][2][4];
            #pragma unroll
            for (int mt = 0; mt < 2; mt++)
                #pragma unroll
                for (int kk = 0; kk < 2; kk++) {
                    #pragma unroll
                    for (int q = 0; q < 4; q++) {
                        int j = 2 * kk + (q >> 1);
                        int r0 = (q & 1) * 2;
                        float x0 = p[mt][j][r0], x1 = p[mt][j][r0 + 1];
                        __nv_bfloat162 hh = __floats2bfloat162_rn(x0, x1);
                        Phi[mt][kk][q] = *(uint32_t*)&hh;
                        Plo[mt][kk][q] = pack_bf16x2(x0 - __bfloat162float(hh.x),
                                                     x1 - __bfloat162float(hh.y));
                    }
                }

            #pragma unroll
            for (int djp = 0; djp < 4; djp++) {
                #pragma unroll
                for (int kk = 0; kk < 2; kk++) {
                    int vrow = kk * 16 + (lane & 7) + 8 * ((lane >> 3) & 1);
                    int chunk = djp * 2 + (lane >> 4);
                    uint32_t ad = (uint32_t)(vrow * 128 + ((chunk ^ (vrow & 7)) << 4));
                    uint32_t h0, h1, h2, h3, l0, l1, l2, l3;
                    ldsm4t(h0, h1, h2, h3, VH + ad);
                    ldsm4t(l0, l1, l2, l3, VL + ad);
                    #pragma unroll
                    for (int mt = 0; mt < 2; mt++) {
                        float* o0 = O[mt][djp * 2];
                        float* o1 = O[mt][djp * 2 + 1];
                        mma_bf16(o0[0], o0[1], o0[2], o0[3],
                                 Phi[mt][kk][0], Phi[mt][kk][1], Phi[mt][kk][2], Phi[mt][kk][3],
                                 h0, h1);
                        mma_bf16(o0[0], o0[1], o0[2], o0[3],
                                 Plo[mt][kk][0], Plo[mt][kk][1], Plo[mt][kk][2], Plo[mt][kk][3],
                                 h0, h1);
                        mma_bf16(o0[0], o0[1], o0[2], o0[3],
                                 Phi[mt][kk][0], Phi[mt][kk][1], Phi[mt][kk][2], Phi[mt][kk][3],
                                 l0, l1);
                        mma_bf16(o1[0], o1[1], o1[2], o1[3],
                                 Phi[mt][kk][0], Phi[mt][kk][1], Phi[mt][kk][2], Phi[mt][kk][3],
                                 h2, h3);
                        mma_bf16(o1[0], o1[1], o1[2], o1[3],
                                 Plo[mt][kk][0], Plo[mt][kk][1], Plo[mt][kk][2], Plo[mt][kk][3],
                                 h2, h3);
                        mma_bf16(o1[0], o1[1], o1[2], o1[3],
                                 Phi[mt][kk][0], Phi[mt][kk][1], Phi[mt][kk][2], Phi[mt][kk][3],
                                 l2, l3);
                    }
                }
            }
        }
        __syncthreads();
    }

    #pragma unroll
    for (int mt = 0; mt < 2; mt++) {
        float invA = (lrow[mt][0] > 0.0f) ? (1.0f / lrow[mt][0]) : 0.0f;
        float invB = (lrow[mt][1] > 0.0f) ? (1.0f / lrow[mt][1]) : 0.0f;
        int rA = q0 + mBase + mt * 16 + gid;
        int rB = rA + 8;
        #pragma unroll
        for (int dj = 0; dj < 8; dj++) {
            int col = h * 64 + dj * 8 + tig * 2;
            float v0 = O[mt][dj][0] * invA, v1 = O[mt][dj][1] * invA;
            float v2 = O[mt][dj][2] * invB, v3 = O[mt][dj][3] * invB;
            size_t iA = ((size_t)rA * DIM + col) >> 1;
            size_t iB = ((size_t)rB * DIM + col) >> 1;
            __nv_bfloat162 hA = __floats2bfloat162_rn(v0, v1);
            __nv_bfloat162 hB = __floats2bfloat162_rn(v2, v3);
            ((uint32_t*)oh)[iA] = *(uint32_t*)&hA;
            ((uint32_t*)oh)[iB] = *(uint32_t*)&hB;
            ((uint32_t*)ol)[iA] = pack_bf16x2(v0 - __bfloat162float(hA.x),
                                              v1 - __bfloat162float(hA.y));
            ((uint32_t*)ol)[iB] = pack_bf16x2(v2 - __bfloat162float(hB.x),
                                              v3 - __bfloat162float(hB.y));
        }
    }
}

// ---------------- classification heads (768 -> 512 relu -> nout) ------------
__global__ void head_kernel(const float* __restrict__ x, const float* __restrict__ W1,
                            const float* __restrict__ b1, const float* __restrict__ W2,
                            const float* __restrict__ b2, float* __restrict__ out, int nout) {
    __shared__ float xs[768];
    __shared__ float hsm[512];
    int t = threadIdx.x;
    for (int i = t; i < 768; i += 512) xs[i] = x[i];
    __syncthreads();
    float acc = b1[t];
    for (int kk = 0; kk < 768; kk++) acc += xs[kk] * W1[(size_t)kk * 512 + t];
    hsm[t] = fmaxf(acc, 0.0f);
    __syncthreads();
    if (t < nout) {
        float ov = b2[t];
        for (int kk = 0; kk < 512; kk++) ov += hsm[kk] * W2[(size_t)kk * nout + t];
        out[t] = ov;
    }
}

// ---------------- host launcher ---------------------------------------------
extern "C" void kernel_launch(void* const* d_in, const int* in_sizes, int n_in,
                              void* d_out, int out_size) {
    const int*   ids      = (const int*)d_in[0];
    const int*   mask     = (const int*)d_in[1];
    const float* emb_word = (const float*)d_in[2];
    const float* emb_pos  = (const float*)d_in[3];
    const float* emb_type = (const float*)d_in[4];
    const float* emb_g    = (const float*)d_in[5];
    const float* emb_b    = (const float*)d_in[6];
    const float* Wq = (const float*)d_in[7];
    const float* bq = (const float*)d_in[8];
    const float* Wk = (const float*)d_in[9];
    const float* bk = (const float*)d_in[10];
    const float* Wv = (const float*)d_in[11];
    const float* bv = (const float*)d_in[12];
    const float* Wo = (const float*)d_in[13];
    const float* bo = (const float*)d_in[14];
    const float* ln1g = (const float*)d_in[15];
    const float* ln1b = (const float*)d_in[16];
    const float* W1 = (const float*)d_in[17];
    const float* b1 = (const float*)d_in[18];
    const float* W2 = (const float*)d_in[19];
    const float* b2 = (const float*)d_in[20];
    const float* ln2g = (const float*)d_in[21];
    const float* ln2b = (const float*)d_in[22];
    const float* cW1 = (const float*)d_in[23];
    const float* cb1 = (const float*)d_in[24];
    const float* cW2 = (const float*)d_in[25];
    const float* cb2 = (const float*)d_in[26];
    const float* dW1 = (const float*)d_in[27];
    const float* db1 = (const float*)d_in[28];
    const float* dW2 = (const float*)d_in[29];
    const float* db2 = (const float*)d_in[30];
    float* out = (float*)d_out;

    float *x, *qkv, *t, *bcat;
    int* pos;
    __nv_bfloat16 *xh, *xl, *ah, *al, *hh, *hl;
    __nv_bfloat16 *wqh, *wql, *w1h, *w1l, *w2h, *w2l, *woh, *wol;
    cudaGetSymbolAddress((void**)&x, g_x);
    cudaGetSymbolAddress((void**)&qkv, g_qkv);
    cudaGetSymbolAddress((void**)&t, g_t);
    cudaGetSymbolAddress((void**)&bcat, g_bcat);
    cudaGetSymbolAddress((void**)&pos, g_pos);
    cudaGetSymbolAddress((void**)&xh, g_xh);
    cudaGetSymbolAddress((void**)&xl, g_xl);
    cudaGetSymbolAddress((void**)&ah, g_ah);
    cudaGetSymbolAddress((void**)&al, g_al);
    cudaGetSymbolAddress((void**)&hh, g_hh);
    cudaGetSymbolAddress((void**)&hl, g_hl);
    cudaGetSymbolAddress((void**)&wqh, g_wqh);
    cudaGetSymbolAddress((void**)&wql, g_wql);
    cudaGetSymbolAddress((void**)&w1h, g_w1h);
    cudaGetSymbolAddress((void**)&w1l, g_w1l);
    cudaGetSymbolAddress((void**)&w2h, g_w2h);
    cudaGetSymbolAddress((void**)&w2l, g_w2l);
    cudaGetSymbolAddress((void**)&woh, g_woh);
    cudaGetSymbolAddress((void**)&wol, g_wol);

    cudaFuncSetAttribute(attn_mma_kernel, cudaFuncAttributeMaxDynamicSharedMemorySize, ATT_SMEM);

    pos_kernel<<<1, 1024>>>(mask, pos);
    embed_ln_kernel<<<SEQ, 256>>>(ids, pos, emb_word, emb_pos, emb_type, emb_g, emb_b, x, xh, xl);

    dim3 gqkv(3 * DIM / 128, SEQ / 128);   // (18, 32)
    dim3 go(DIM / 128, SEQ / 64);          // (6, 64) BM=64
    dim3 gff1(FFD / 128, SEQ / 128);       // (24, 32)
    dim3 gff2(DIM / 128, SEQ / 64);        // (6, 64) BM=64
    dim3 gattn(SEQ / 128, NH);
    int cgrid = (DIM * DIM / 4 + 255) / 256;

    // ---- hoisted weight prep: all layers upfront (DRAM-bound, back-to-back) ----
    for (int i = 0; i < NL; i++) {
        const float* wq = Wq + (size_t)i * DIM * DIM;
        const float* wk = Wk + (size_t)i * DIM * DIM;
        const float* wv = Wv + (size_t)i * DIM * DIM;
        const float* wo = Wo + (size_t)i * DIM * DIM;
        const float* w1 = W1 + (size_t)i * DIM * FFD;
        const float* w2 = W2 + (size_t)i * FFD * DIM;
        concat_qkv_kernel<<<cgrid, 256>>>(wq, wk, wv, bq + i * DIM, bk + i * DIM, bv + i * DIM,
                                          wqh + (size_t)i * DIM * 3 * DIM,
                                          wql + (size_t)i * DIM * 3 * DIM,
                                          bcat + (size_t)i * 3 * DIM);
        split_kernel<<<(DIM * FFD / 4 + 255) / 256, 256>>>(w1, w1h + (size_t)i * DIM * FFD,
                                                           w1l + (size_t)i * DIM * FFD,
                                                           DIM * FFD / 4);
        split_kernel<<<(FFD * DIM / 4 + 255) / 256, 256>>>(w2, w2h + (size_t)i * FFD * DIM,
                                                           w2l + (size_t)i * FFD * DIM,
                                                           FFD * DIM / 4);
        split_kernel<<<(DIM * DIM / 4 + 255) / 256, 256>>>(wo, woh + (size_t)i * DIM * DIM,
                                                           wol + (size_t)i * DIM * DIM,
                                                           DIM * DIM / 4);
    }

    for (int i = 0; i < NL; i++) {
        tgemm_kernel<128, 0><<<gqkv, 256>>>(xh, xl,
                                            wqh + (size_t)i * DIM * 3 * DIM,
                                            wql + (size_t)i * DIM * 3 * DIM,
                                            bcat + (size_t)i * 3 * DIM, qkv, nullptr, nullptr,
                                            SEQ, 3 * DIM, DIM);
        attn_mma_kernel<<<gattn, 128, ATT_SMEM>>>(qkv, mask, ah, al);
        tgemm_kernel<64, 0><<<go, 256>>>(ah, al,
                                         woh + (size_t)i * DIM * DIM,
                                         wol + (size_t)i * DIM * DIM,
                                         bo + i * DIM, t, nullptr, nullptr,
                                         SEQ, DIM, DIM);
        lnres_kernel<<<SEQ, 256>>>(x, t, ln1g + i * DIM, ln1b + i * DIM, xh, xl);
        tgemm_kernel<128, 2><<<gff1, 256>>>(xh, xl,
                                            w1h + (size_t)i * DIM * FFD,
                                            w1l + (size_t)i * DIM * FFD,
                                            b1 + i * FFD, nullptr, hh, hl,
                                            SEQ, FFD, DIM);
        tgemm_kernel<64, 0><<<gff2, 256>>>(hh, hl,
                                           w2h + (size_t)i * FFD * DIM,
                                           w2l + (size_t)i * FFD * DIM,
                                           b2 + i * DIM, t, nullptr, nullptr,
                                           SEQ, DIM, FFD);
        lnres_kernel<<<SEQ, 256>>>(x, t, ln2g + i * DIM, ln2b + i * DIM, xh, xl);
    }

    head_kernel<<<1, 512>>>(x, cW1, cb1, cW2, cb2, out, 5);
    head_kernel<<<1, 512>>>(x, dW1, db1, dW2, db2, out + 5, 10);
}

// round 10
// speedup vs baseline: 1.1819x; 1.1819x over previous
#include <cuda_runtime.h>
#include <cuda_bf16.h>
#include <stdint.h>
#include <math.h>

#define SEQ 4096
#define DIM 768
#define NH  12
#define HD  64
#define NL  12
#define FFD 3072
#define WIN 256
#define EPSF 1e-5f

// ---------------- scratch (static device globals; no runtime allocation) ----
__device__ float g_x[SEQ * DIM];
__device__ float g_qkv[SEQ * 3 * DIM];
__device__ float g_t[SEQ * DIM];
__device__ float g_bcat[3 * DIM];
__device__ int   g_pos[SEQ];

__device__ __nv_bfloat16 g_xh[SEQ * DIM],  g_xl[SEQ * DIM];
__device__ __nv_bfloat16 g_ah[SEQ * DIM],  g_al[SEQ * DIM];
__device__ __nv_bfloat16 g_hh[SEQ * FFD],  g_hl[SEQ * FFD];
__device__ __nv_bfloat16 g_wqh[DIM * 3 * DIM], g_wql[DIM * 3 * DIM];
__device__ __nv_bfloat16 g_w1h[DIM * FFD], g_w1l[DIM * FFD];
__device__ __nv_bfloat16 g_w2h[FFD * DIM], g_w2l[FFD * DIM];
__device__ __nv_bfloat16 g_woh[DIM * DIM], g_wol[DIM * DIM];

// ---------------- helpers ---------------------------------------------------
__device__ __forceinline__ float gelu_exact(float x) {
    return 0.5f * x * (1.0f + erff(x * 0.70710678118654752f));
}

__device__ __forceinline__ uint32_t pack_bf16x2(float x, float y) {
    __nv_bfloat162 h = __floats2bfloat162_rn(x, y);
    return *(uint32_t*)&h;
}

__device__ __forceinline__ void mma_bf16(float& d0, float& d1, float& d2, float& d3,
                                         uint32_t a0, uint32_t a1, uint32_t a2, uint32_t a3,
                                         uint32_t b0, uint32_t b1) {
    asm volatile("mma.sync.aligned.m16n8k16.row.col.f32.bf16.bf16.f32 "
                 "{%0,%1,%2,%3}, {%4,%5,%6,%7}, {%8,%9}, {%0,%1,%2,%3};"
                 : "+f"(d0), "+f"(d1), "+f"(d2), "+f"(d3)
                 : "r"(a0), "r"(a1), "r"(a2), "r"(a3), "r"(b0), "r"(b1));
}

__device__ __forceinline__ void ldsm4(uint32_t& r0, uint32_t& r1, uint32_t& r2, uint32_t& r3,
                                      uint32_t addr) {
    asm volatile("ldmatrix.sync.aligned.m8n8.x4.shared.b16 {%0,%1,%2,%3}, [%4];"
                 : "=r"(r0), "=r"(r1), "=r"(r2), "=r"(r3) : "r"(addr));
}

__device__ __forceinline__ void ldsm4t(uint32_t& r0, uint32_t& r1, uint32_t& r2, uint32_t& r3,
                                       uint32_t addr) {
    asm volatile("ldmatrix.sync.aligned.m8n8.x4.trans.shared.b16 {%0,%1,%2,%3}, [%4];"
                 : "=r"(r0), "=r"(r1), "=r"(r2), "=r"(r3) : "r"(addr));
}

__device__ __forceinline__ void cp16(uint32_t saddr, const void* gaddr) {
    asm volatile("cp.async.cg.shared.global [%0], [%1], 16;" :: "r"(saddr), "l"(gaddr));
}

__device__ __forceinline__ void split_store8(char* hp, char* lp, float4 v) {
    __nv_bfloat162 h01 = __floats2bfloat162_rn(v.x, v.y);
    __nv_bfloat162 h23 = __floats2bfloat162_rn(v.z, v.w);
    uint2 hh;
    hh.x = *(uint32_t*)&h01;
    hh.y = *(uint32_t*)&h23;
    uint2 ll;
    ll.x = pack_bf16x2(v.x - __bfloat162float(h01.x), v.y - __bfloat162float(h01.y));
    ll.y = pack_bf16x2(v.z - __bfloat162float(h23.x), v.w - __bfloat162float(h23.y));
    *(uint2*)hp = hh;
    *(uint2*)lp = ll;
}

__device__ __forceinline__ float blk_sum256(float v, float* red) {
    #pragma unroll
    for (int o = 16; o > 0; o >>= 1) v += __shfl_down_sync(0xffffffffu, v, o);
    int w = threadIdx.x >> 5;
    if ((threadIdx.x & 31) == 0) red[w] = v;
    __syncthreads();
    if (threadIdx.x < 32) {
        v = (threadIdx.x < 8) ? red[threadIdx.x] : 0.0f;
        #pragma unroll
        for (int o = 4; o > 0; o >>= 1) v += __shfl_down_sync(0xffffffffu, v, o);
        if (threadIdx.x == 0) red[0] = v;
    }
    __syncthreads();
    float r = red[0];
    __syncthreads();
    return r;
}

// ---------------- pos_ids = cumsum(mask)*mask + 1 ---------------------------
__global__ void pos_kernel(const int* __restrict__ mask, int* __restrict__ pos) {
    __shared__ int ss[1024];
    int t = threadIdx.x;
    int m0 = mask[t * 4 + 0], m1 = mask[t * 4 + 1];
    int m2 = mask[t * 4 + 2], m3 = mask[t * 4 + 3];
    int s = m0 + m1 + m2 + m3;
    ss[t] = s;
    __syncthreads();
    for (int off = 1; off < 1024; off <<= 1) {
        int vprev = (t >= off) ? ss[t - off] : 0;
        __syncthreads();
        ss[t] += vprev;
        __syncthreads();
    }
    int run = ss[t] - s;
    run += m0; pos[t * 4 + 0] = run * m0 + 1;
    run += m1; pos[t * 4 + 1] = run * m1 + 1;
    run += m2; pos[t * 4 + 2] = run * m2 + 1;
    run += m3; pos[t * 4 + 3] = run * m3 + 1;
}

// ---------------- embedding + layernorm (writes f32 + bf16 hi/lo) -----------
__global__ void embed_ln_kernel(const int* __restrict__ ids, const int* __restrict__ pos,
                                const float* __restrict__ ew, const float* __restrict__ ep,
                                const float* __restrict__ et, const float* __restrict__ g,
                                const float* __restrict__ b, float* __restrict__ x,
                                __nv_bfloat16* __restrict__ xh, __nv_bfloat16* __restrict__ xl) {
    __shared__ float red[32];
    int srow = blockIdx.x;
    int t = threadIdx.x;
    int wid = ids[srow];
    int pid = pos[srow];
    float val[3];
    #pragma unroll
    for (int r = 0; r < 3; r++) {
        int i = t + r * 256;
        val[r] = ew[(size_t)wid * DIM + i] + ep[(size_t)pid * DIM + i] + et[i];
    }
    float mu = blk_sum256(val[0] + val[1] + val[2], red) * (1.0f / DIM);
    float vs = 0.0f;
    #pragma unroll
    for (int r = 0; r < 3; r++) { float d = val[r] - mu; vs += d * d; }
    float var = blk_sum256(vs, red) * (1.0f / DIM);
    float rs = rsqrtf(var + EPSF);
    #pragma unroll
    for (int r = 0; r < 3; r++) {
        int i = t + r * 256;
        float y = (val[r] - mu) * rs * g[i] + b[i];
        size_t idx = (size_t)srow * DIM + i;
        x[idx] = y;
        __nv_bfloat16 h = __float2bfloat16_rn(y);
        xh[idx] = h;
        xl[idx] = __float2bfloat16_rn(y - __bfloat162float(h));
    }
}

// ---------------- x = LN(x + delta), writes f32 + bf16 hi/lo -----------------
__global__ void lnres_kernel(float* __restrict__ x, const float* __restrict__ delta,
                             const float* __restrict__ g, const float* __restrict__ b,
                             __nv_bfloat16* __restrict__ xh, __nv_bfloat16* __restrict__ xl) {
    __shared__ float red[32];
    int srow = blockIdx.x;
    int t = threadIdx.x;
    float val[3];
    #pragma unroll
    for (int r = 0; r < 3; r++) {
        int i = t + r * 256;
        val[r] = x[(size_t)srow * DIM + i] + delta[(size_t)srow * DIM + i];
    }
    float mu = blk_sum256(val[0] + val[1] + val[2], red) * (1.0f / DIM);
    float vs = 0.0f;
    #pragma unroll
    for (int r = 0; r < 3; r++) { float d = val[r] - mu; vs += d * d; }
    float var = blk_sum256(vs, red) * (1.0f / DIM);
    float rs = rsqrtf(var + EPSF);
    #pragma unroll
    for (int r = 0; r < 3; r++) {
        int i = t + r * 256;
        float y = (val[r] - mu) * rs * g[i] + b[i];
        size_t idx = (size_t)srow * DIM + i;
        x[idx] = y;
        __nv_bfloat16 h = __float2bfloat16_rn(y);
        xh[idx] = h;
        xl[idx] = __float2bfloat16_rn(y - __bfloat162float(h));
    }
}

// ---------------- generic f32 -> bf16 hi/lo split -----------------------------
__global__ void split_kernel(const float* __restrict__ s, __nv_bfloat16* __restrict__ hi,
                             __nv_bfloat16* __restrict__ lo, int n4) {
    int i = blockIdx.x * blockDim.x + threadIdx.x;
    if (i >= n4) return;
    float4 v = ((const float4*)s)[i];
    __nv_bfloat16 h0 = __float2bfloat16_rn(v.x), h1 = __float2bfloat16_rn(v.y);
    __nv_bfloat16 h2 = __float2bfloat16_rn(v.z), h3 = __float2bfloat16_rn(v.w);
    uint2 hp, lp;
    hp.x = ((uint32_t)*(uint16_t*)&h0) | ((uint32_t)*(uint16_t*)&h1 << 16);
    hp.y = ((uint32_t)*(uint16_t*)&h2) | ((uint32_t)*(uint16_t*)&h3 << 16);
    lp.x = pack_bf16x2(v.x - __bfloat162float(h0), v.y - __bfloat162float(h1));
    lp.y = pack_bf16x2(v.z - __bfloat162float(h2), v.w - __bfloat162float(h3));
    ((uint2*)hi)[i] = hp;
    ((uint2*)lo)[i] = lp;
}

// ---------------- concat QKV weights (split to bf16) + bias ------------------
__global__ void concat_qkv_kernel(const float* __restrict__ Wq, const float* __restrict__ Wk,
                                  const float* __restrict__ Wv, const float* __restrict__ bq,
                                  const float* __restrict__ bk, const float* __restrict__ bv,
                                  __nv_bfloat16* __restrict__ Wh, __nv_bfloat16* __restrict__ Wl,
                                  float* __restrict__ bc) {
    int i4 = blockIdx.x * blockDim.x + threadIdx.x;
    if (i4 < DIM * DIM / 4) {
        int k = i4 / (DIM / 4);
        int n4 = i4 % (DIM / 4);
        const float* srcs[3] = {Wq, Wk, Wv};
        #pragma unroll
        for (int s = 0; s < 3; s++) {
            float4 v = ((const float4*)srcs[s])[i4];
            __nv_bfloat16 h0 = __float2bfloat16_rn(v.x), h1 = __float2bfloat16_rn(v.y);
            __nv_bfloat16 h2 = __float2bfloat16_rn(v.z), h3 = __float2bfloat16_rn(v.w);
            uint2 hp, lp;
            hp.x = ((uint32_t)*(uint16_t*)&h0) | ((uint32_t)*(uint16_t*)&h1 << 16);
            hp.y = ((uint32_t)*(uint16_t*)&h2) | ((uint32_t)*(uint16_t*)&h3 << 16);
            lp.x = pack_bf16x2(v.x - __bfloat162float(h0), v.y - __bfloat162float(h1));
            lp.y = pack_bf16x2(v.z - __bfloat162float(h2), v.w - __bfloat162float(h3));
            int e = k * 3 * DIM + s * DIM + n4 * 4;
            ((uint2*)Wh)[e >> 2] = hp;
            ((uint2*)Wl)[e >> 2] = lp;
        }
    }
    if (i4 < DIM / 4) {
        ((float4*)bc)[i4] = ((const float4*)bq)[i4];
        ((float4*)(bc + DIM))[i4] = ((const float4*)bk)[i4];
        ((float4*)(bc + 2 * DIM))[i4] = ((const float4*)bv)[i4];
    }
}

// ---------------- bf16x3 tensor-core GEMM (BK=32, cp.async + ldmatrix) -------
// C[M,N] = A[M,K] @ B[K,N] + bias. A,B pre-split into bf16 hi/lo in gmem.
// acc = hiA*hiB + hiA*loB + loA*hiB (3 MMAs, fp32-comparable accuracy).
// BN=128, 256 threads (8 warps), k32 stages (2x k16 sub-steps), 2-stage pipeline.
// A smem: [BM][32] bf16, 64B rows, chunk swizzle ch^((row>>1)&3) -> conflict-free ldsm.
// B smem: [32][128] bf16 k-major, chunk swizzle ch^(krow&7) -> conflict-free ldsm.trans.
template <int BM, int OUT>
__global__ __launch_bounds__(256) void tgemm_kernel(
    const __nv_bfloat16* __restrict__ Ah, const __nv_bfloat16* __restrict__ Al,
    const __nv_bfloat16* __restrict__ Bh, const __nv_bfloat16* __restrict__ Bl,
    const float* __restrict__ bias, float* __restrict__ C,
    __nv_bfloat16* __restrict__ Chi, __nv_bfloat16* __restrict__ Clo,
    int M, int N, int K) {
    constexpr int MT = BM / 64;
    constexpr int OFF_AL = BM * 64;
    constexpr int OFF_BH = 2 * BM * 64;
    constexpr int OFF_BL = 2 * BM * 64 + 8192;
    constexpr int STAGE  = 2 * BM * 64 + 16384;
    constexpr int AITERS = BM * 4 / 256;   // 16B chunks of A per thread (1 or 2)

    extern __shared__ __align__(16) unsigned char smem_raw[];
    uint32_t smemb = (uint32_t)__cvta_generic_to_shared(smem_raw);

    const int bx = blockIdx.x;
    const int by = blockIdx.y;
    const int tid = threadIdx.x;
    const int lane = tid & 31;
    const int wid = tid >> 5;
    const int warpM = wid & 3;
    const int warpN = wid >> 2;
    const int gid = lane >> 2;
    const int tig = lane & 3;
    const int mBase = warpM * 16 * MT;
    const int nBase = warpN * 64;
    const int rowbase = by * BM;
    const int colbase = bx * 128;

    float acc[MT][8][4];
    #pragma unroll
    for (int mt = 0; mt < MT; mt++)
        #pragma unroll
        for (int nt = 0; nt < 8; nt++)
            #pragma unroll
            for (int r = 0; r < 4; r++) acc[mt][nt][r] = 0.0f;

    auto issue = [&](int st, int k0) {
        uint32_t sb = smemb + st * STAGE;
        #pragma unroll
        for (int it = 0; it < AITERS; it++) {
            int idx = tid + it * 256;
            int r = idx >> 2, ch = idx & 3;
            size_t go = (size_t)(rowbase + r) * K + k0 + ch * 8;
            uint32_t so = (uint32_t)(r * 64 + ((ch ^ ((r >> 1) & 3)) << 4));
            cp16(sb + so, Ah + go);
            cp16(sb + OFF_AL + so, Al + go);
        }
        #pragma unroll
        for (int it = 0; it < 2; it++) {
            int idx = tid + it * 256;
            int krow = idx >> 4, ch = idx & 15;
            size_t go = (size_t)(k0 + krow) * N + colbase + ch * 8;
            uint32_t so = (uint32_t)(krow * 256 + ((ch ^ (krow & 7)) << 4));
            cp16(sb + OFF_BH + so, Bh + go);
            cp16(sb + OFF_BL + so, Bl + go);
        }
    };

    const int KT = K >> 5;     // k32 steps
    issue(0, 0);
    asm volatile("cp.async.commit_group;" ::: "memory");

    const int lane15 = lane & 15;
    const int laneh = lane >> 4;
    const int bk = lane & 15;
    const int bs = (lane >> 4) & 1;

    for (int t = 0; t < KT; t++) {
        if (t + 1 < KT) {
            issue((t + 1) & 1, (t + 1) * 32);
            asm volatile("cp.async.commit_group;" ::: "memory");
            asm volatile("cp.async.wait_group 1;" ::: "memory");
        } else {
            asm volatile("cp.async.wait_group 0;" ::: "memory");
        }
        __syncthreads();

        uint32_t sb = smemb + (t & 1) * STAGE;
        #pragma unroll
        for (int kk = 0; kk < 2; kk++) {
            // A fragments: logical chunk = kk*2 + laneh, row-dependent swizzle
            uint32_t aHi[MT][4], aLo[MT][4];
            #pragma unroll
            for (int mt = 0; mt < MT; mt++) {
                int row = mBase + mt * 16 + lane15;
                int ch = (kk * 2 + laneh) ^ ((row >> 1) & 3);
                uint32_t ad = sb + (uint32_t)(row * 64 + (ch << 4));
                ldsm4(aHi[mt][0], aHi[mt][1], aHi[mt][2], aHi[mt][3], ad);
                ldsm4(aLo[mt][0], aLo[mt][1], aLo[mt][2], aLo[mt][3], ad + OFF_AL);
            }
            int krow = kk * 16 + bk;
            uint32_t bRow = sb + OFF_BH + (uint32_t)(krow * 256);
            #pragma unroll
            for (int nt2 = 0; nt2 < 4; nt2++) {
                uint32_t ch = (uint32_t)((((warpN * 8 + nt2 * 2 + bs) ^ (bk & 7))) * 16);
                uint32_t bh0, bh1, bh2, bh3, bl0, bl1, bl2, bl3;
                ldsm4t(bh0, bh1, bh2, bh3, bRow + ch);
                ldsm4t(bl0, bl1, bl2, bl3, bRow + (OFF_BL - OFF_BH) + ch);
                #pragma unroll
                for (int mt = 0; mt < MT; mt++) {
                    float* a0 = acc[mt][nt2 * 2];
                    mma_bf16(a0[0], a0[1], a0[2], a0[3],
                             aHi[mt][0], aHi[mt][1], aHi[mt][2], aHi[mt][3], bh0, bh1);
                    mma_bf16(a0[0], a0[1], a0[2], a0[3],
                             aHi[mt][0], aHi[mt][1], aHi[mt][2], aHi[mt][3], bl0, bl1);
                    mma_bf16(a0[0], a0[1], a0[2], a0[3],
                             aLo[mt][0], aLo[mt][1], aLo[mt][2], aLo[mt][3], bh0, bh1);
                    float* a1 = acc[mt][nt2 * 2 + 1];
                    mma_bf16(a1[0], a1[1], a1[2], a1[3],
                             aHi[mt][0], aHi[mt][1], aHi[mt][2], aHi[mt][3], bh2, bh3);
                    mma_bf16(a1[0], a1[1], a1[2], a1[3],
                             aHi[mt][0], aHi[mt][1], aHi[mt][2], aHi[mt][3], bl2, bl3);
                    mma_bf16(a1[0], a1[1], a1[2], a1[3],
                             aLo[mt][0], aLo[mt][1], aLo[mt][2], aLo[mt][3], bh2, bh3);
                }
            }
        }
        __syncthreads();
    }

    #pragma unroll
    for (int nt = 0; nt < 8; nt++) {
        int col = colbase + nBase + nt * 8 + tig * 2;
        float b0 = bias[col], b1 = bias[col + 1];
        #pragma unroll
        for (int mt = 0; mt < MT; mt++) {
            int row0 = rowbase + mBase + mt * 16 + gid;
            float v0 = acc[mt][nt][0] + b0;
            float v1 = acc[mt][nt][1] + b1;
            float v2 = acc[mt][nt][2] + b0;
            float v3 = acc[mt][nt][3] + b1;
            if (OUT == 0) {
                *(float2*)(C + (size_t)row0 * N + col) = make_float2(v0, v1);
                *(float2*)(C + (size_t)(row0 + 8) * N + col) = make_float2(v2, v3);
            } else {
                v0 = gelu_exact(v0); v1 = gelu_exact(v1);
                v2 = gelu_exact(v2); v3 = gelu_exact(v3);
                size_t i0 = ((size_t)row0 * N + col) >> 1;
                size_t i1 = ((size_t)(row0 + 8) * N + col) >> 1;
                __nv_bfloat16 h0 = __float2bfloat16_rn(v0), h1 = __float2bfloat16_rn(v1);
                __nv_bfloat16 h2 = __float2bfloat16_rn(v2), h3 = __float2bfloat16_rn(v3);
                ((uint32_t*)Chi)[i0] = ((uint32_t)*(uint16_t*)&h0) | ((uint32_t)*(uint16_t*)&h1 << 16);
                ((uint32_t*)Chi)[i1] = ((uint32_t)*(uint16_t*)&h2) | ((uint32_t)*(uint16_t*)&h3 << 16);
                ((uint32_t*)Clo)[i0] = pack_bf16x2(v0 - __bfloat162float(h0), v1 - __bfloat162float(h1));
                ((uint32_t*)Clo)[i1] = pack_bf16x2(v2 - __bfloat162float(h2), v3 - __bfloat162float(h3));
            }
        }
    }
}

// ---------------- tensor-core sliding-window flash attention -----------------
#define ATT_SMEM (49152 + 128)
__global__ __launch_bounds__(128) void attn_mma_kernel(
    const float* __restrict__ qkv, const int* __restrict__ mask,
    __nv_bfloat16* __restrict__ oh, __nv_bfloat16* __restrict__ ol) {
    extern __shared__ __align__(16) unsigned char asmem[];
    char* gp = (char*)asmem;
    const uint32_t sb = (uint32_t)__cvta_generic_to_shared(asmem);
    const uint32_t QH = sb, QL = sb + 16384;
    const uint32_t KH = sb + 32768, KL = KH + 4096, VH = KL + 4096, VL = VH + 4096;
    char* gQH = gp; char* gQL = gp + 16384;
    char* gKH = gp + 32768; char* gKL = gKH + 4096;
    char* gVH = gKL + 4096; char* gVL = gVH + 4096;
    int* msk = (int*)(gp + 49152);

    const int h = blockIdx.y;
    const int q0 = blockIdx.x * 128;
    const int tid = threadIdx.x, lane = tid & 31, wid = tid >> 5;
    const int gid = lane >> 2, tig = lane & 3;
    const int mBase = wid * 32;
    const int STR = 3 * DIM;

    #pragma unroll
    for (int i = 0; i < 16; i++) {
        int f = tid + i * 128;
        int row = f >> 4, col4 = f & 15;
        float4 q4 = *(const float4*)(qkv + (size_t)(q0 + row) * STR + h * 64 + col4 * 4);
        q4.x *= 0.125f; q4.y *= 0.125f; q4.z *= 0.125f; q4.w *= 0.125f;
        int chunk = col4 >> 1, half = col4 & 1;
        int off = row * 128 + ((chunk ^ (row & 7)) << 4) + half * 8;
        split_store8(gQH + off, gQL + off, q4);
    }
    __syncthreads();

    uint32_t Qhi[2][4][4], Qlo[2][4][4];
    {
        int arow = (lane & 7) + 8 * ((lane >> 3) & 1);
        int achsel = lane >> 4;
        #pragma unroll
        for (int mt = 0; mt < 2; mt++) {
            int row = mBase + mt * 16 + arow;
            #pragma unroll
            for (int kk = 0; kk < 4; kk++) {
                int chunk = kk * 2 + achsel;
                uint32_t ad = (uint32_t)(row * 128 + ((chunk ^ (row & 7)) << 4));
                ldsm4(Qhi[mt][kk][0], Qhi[mt][kk][1], Qhi[mt][kk][2], Qhi[mt][kk][3], QH + ad);
                ldsm4(Qlo[mt][kk][0], Qlo[mt][kk][1], Qlo[mt][kk][2], Qlo[mt][kk][3], QL + ad);
            }
        }
    }

    float O[2][8][4];
    #pragma unroll
    for (int mt = 0; mt < 2; mt++)
        #pragma unroll
        for (int dj = 0; dj < 8; dj++)
            #pragma unroll
            for (int r = 0; r < 4; r++) O[mt][dj][r] = 0.0f;
    float mrow[2][2] = {{-1e30f, -1e30f}, {-1e30f, -1e30f}};
    float lrow[2][2] = {{0.0f, 0.0f}, {0.0f, 0.0f}};

    const int warpLo = q0 + mBase - WIN;
    const int warpHi = q0 + mBase + 31 + WIN;

    for (int c = q0 - WIN; c < q0 + 128 + WIN; c += 32) {
        #pragma unroll
        for (int i = 0; i < 4; i++) {
            int f = tid + i * 128;
            int row = f >> 4, col4 = f & 15;
            int kp = c + row;
            int kc = kp < 0 ? 0 : (kp >= SEQ ? SEQ - 1 : kp);
            float4 kv = *(const float4*)(qkv + (size_t)kc * STR + DIM + h * 64 + col4 * 4);
            float4 vv = *(const float4*)(qkv + (size_t)kc * STR + 2 * DIM + h * 64 + col4 * 4);
            int chunk = col4 >> 1, half = col4 & 1;
            int off = row * 128 + ((chunk ^ (row & 7)) << 4) + half * 8;
            split_store8(gKH + off, gKL + off, kv);
            split_store8(gVH + off, gVL + off, vv);
        }
        if (tid < 32) {
            int kp = c + tid;
            msk[tid] = (kp >= 0 && kp < SEQ) ? mask[kp] : 0;
        }
        __syncthreads();

        if (c + 31 >= warpLo && c <= warpHi) {
            float S[2][4][4];
            #pragma unroll
            for (int mt = 0; mt < 2; mt++)
                #pragma unroll
                for (int j = 0; j < 4; j++)
                    #pragma unroll
                    for (int r = 0; r < 4; r++) S[mt][j][r] = 0.0f;

            #pragma unroll
            for (int j = 0; j < 4; j++) {
                uint32_t kh[4][2], kl[4][2];
                int krow = j * 8 + (lane & 7);
                #pragma unroll
                for (int h32 = 0; h32 < 2; h32++) {
                    int chunk = h32 * 4 + (lane >> 3);
                    uint32_t ad = (uint32_t)(krow * 128 + ((chunk ^ (krow & 7)) << 4));
                    uint32_t r0, r1, r2, r3;
                    ldsm4(r0, r1, r2, r3, KH + ad);
                    kh[h32 * 2][0] = r0; kh[h32 * 2][1] = r1;
                    kh[h32 * 2 + 1][0] = r2; kh[h32 * 2 + 1][1] = r3;
                    ldsm4(r0, r1, r2, r3, KL + ad);
                    kl[h32 * 2][0] = r0; kl[h32 * 2][1] = r1;
                    kl[h32 * 2 + 1][0] = r2; kl[h32 * 2 + 1][1] = r3;
                }
                #pragma unroll
                for (int kk = 0; kk < 4; kk++)
                    #pragma unroll
                    for (int mt = 0; mt < 2; mt++) {
                        float* s = S[mt][j];
                        mma_bf16(s[0], s[1], s[2], s[3],
                                 Qhi[mt][kk][0], Qhi[mt][kk][1], Qhi[mt][kk][2], Qhi[mt][kk][3],
                                 kh[kk][0], kh[kk][1]);
                        mma_bf16(s[0], s[1], s[2], s[3],
                                 Qhi[mt][kk][0], Qhi[mt][kk][1], Qhi[mt][kk][2], Qhi[mt][kk][3],
                                 kl[kk][0], kl[kk][1]);
                        mma_bf16(s[0], s[1], s[2], s[3],
                                 Qlo[mt][kk][0], Qlo[mt][kk][1], Qlo[mt][kk][2], Qlo[mt][kk][3],
                                 kh[kk][0], kh[kk][1]);
                    }
            }

            float p[2][4][4];
            #pragma unroll
            for (int mt = 0; mt < 2; mt++) {
                int rA = q0 + mBase + mt * 16 + gid;
                int rB = rA + 8;
                float mxA = -1e30f, mxB = -1e30f;
                #pragma unroll
                for (int j = 0; j < 4; j++) {
                    int c0 = c + j * 8 + tig * 2;
                    int c1 = c0 + 1;
                    int mk0 = msk[j * 8 + tig * 2];
                    int mk1 = msk[j * 8 + tig * 2 + 1];
                    bool v00 = mk0 && (c0 >= rA - WIN) && (c0 <= rA + WIN);
                    bool v01 = mk1 && (c1 >= rA - WIN) && (c1 <= rA + WIN);
                    bool v10 = mk0 && (c0 >= rB - WIN) && (c0 <= rB + WIN);
                    bool v11 = mk1 && (c1 >= rB - WIN) && (c1 <= rB + WIN);
                    S[mt][j][0] = v00 ? S[mt][j][0] : -1e30f;
                    S[mt][j][1] = v01 ? S[mt][j][1] : -1e30f;
                    S[mt][j][2] = v10 ? S[mt][j][2] : -1e30f;
                    S[mt][j][3] = v11 ? S[mt][j][3] : -1e30f;
                    mxA = fmaxf(mxA, fmaxf(S[mt][j][0], S[mt][j][1]));
                    mxB = fmaxf(mxB, fmaxf(S[mt][j][2], S[mt][j][3]));
                }
                mxA = fmaxf(mxA, __shfl_xor_sync(0xffffffffu, mxA, 1));
                mxA = fmaxf(mxA, __shfl_xor_sync(0xffffffffu, mxA, 2));
                mxB = fmaxf(mxB, __shfl_xor_sync(0xffffffffu, mxB, 1));
                mxB = fmaxf(mxB, __shfl_xor_sync(0xffffffffu, mxB, 2));
                float mnA = fmaxf(mrow[mt][0], mxA);
                float mnB = fmaxf(mrow[mt][1], mxB);
                float scA = __expf(mrow[mt][0] - mnA);
                float scB = __expf(mrow[mt][1] - mnB);
                mrow[mt][0] = mnA; mrow[mt][1] = mnB;
                float sA = 0.0f, sB = 0.0f;
                #pragma unroll
                for (int j = 0; j < 4; j++) {
                    float p0 = (S[mt][j][0] > -1e29f) ? __expf(S[mt][j][0] - mnA) : 0.0f;
                    float p1 = (S[mt][j][1] > -1e29f) ? __expf(S[mt][j][1] - mnA) : 0.0f;
                    float p2 = (S[mt][j][2] > -1e29f) ? __expf(S[mt][j][2] - mnB) : 0.0f;
                    float p3 = (S[mt][j][3] > -1e29f) ? __expf(S[mt][j][3] - mnB) : 0.0f;
                    p[mt][j][0] = p0; p[mt][j][1] = p1; p[mt][j][2] = p2; p[mt][j][3] = p3;
                    sA += p0 + p1; sB += p2 + p3;
                }
                sA += __shfl_xor_sync(0xffffffffu, sA, 1);
                sA += __shfl_xor_sync(0xffffffffu, sA, 2);
                sB += __shfl_xor_sync(0xffffffffu, sB, 1);
                sB += __shfl_xor_sync(0xffffffffu, sB, 2);
                lrow[mt][0] = lrow[mt][0] * scA + sA;
                lrow[mt][1] = lrow[mt][1] * scB + sB;
                #pragma unroll
                for (int dj = 0; dj < 8; dj++) {
                    O[mt][dj][0] *= scA; O[mt][dj][1] *= scA;
                    O[mt][dj][2] *= scB; O[mt][dj][3] *= scB;
                }
            }

            uint32_t Phi[2][2][4], Plo[2][2][4];
            #pragma unroll
            for (int mt = 0; mt < 2; mt++)
                #pragma unroll
                for (int kk = 0; kk < 2; kk++) {
                    #pragma unroll
                    for (int q = 0; q < 4; q++) {
                        int j = 2 * kk + (q >> 1);
                        int r0 = (q & 1) * 2;
                        float x0 = p[mt][j][r0], x1 = p[mt][j][r0 + 1];
                        __nv_bfloat162 hh = __floats2bfloat162_rn(x0, x1);
                        Phi[mt][kk][q] = *(uint32_t*)&hh;
                        Plo[mt][kk][q] = pack_bf16x2(x0 - __bfloat162float(hh.x),
                                                     x1 - __bfloat162float(hh.y));
                    }
                }

            #pragma unroll
            for (int djp = 0; djp < 4; djp++) {
                #pragma unroll
                for (int kk = 0; kk < 2; kk++) {
                    int vrow = kk * 16 + (lane & 7) + 8 * ((lane >> 3) & 1);
                    int chunk = djp * 2 + (lane >> 4);
                    uint32_t ad = (uint32_t)(vrow * 128 + ((chunk ^ (vrow & 7)) << 4));
                    uint32_t h0, h1, h2, h3, l0, l1, l2, l3;
                    ldsm4t(h0, h1, h2, h3, VH + ad);
                    ldsm4t(l0, l1, l2, l3, VL + ad);
                    #pragma unroll
                    for (int mt = 0; mt < 2; mt++) {
                        float* o0 = O[mt][djp * 2];
                        float* o1 = O[mt][djp * 2 + 1];
                        mma_bf16(o0[0], o0[1], o0[2], o0[3],
                                 Phi[mt][kk][0], Phi[mt][kk][1], Phi[mt][kk][2], Phi[mt][kk][3],
                                 h0, h1);
                        mma_bf16(o0[0], o0[1], o0[2], o0[3],
                                 Plo[mt][kk][0], Plo[mt][kk][1], Plo[mt][kk][2], Plo[mt][kk][3],
                                 h0, h1);
                        mma_bf16(o0[0], o0[1], o0[2], o0[3],
                                 Phi[mt][kk][0], Phi[mt][kk][1], Phi[mt][kk][2], Phi[mt][kk][3],
                                 l0, l1);
                        mma_bf16(o1[0], o1[1], o1[2], o1[3],
                                 Phi[mt][kk][0], Phi[mt][kk][1], Phi[mt][kk][2], Phi[mt][kk][3],
                                 h2, h3);
                        mma_bf16(o1[0], o1[1], o1[2], o1[3],
                                 Plo[mt][kk][0], Plo[mt][kk][1], Plo[mt][kk][2], Plo[mt][kk][3],
                                 h2, h3);
                        mma_bf16(o1[0], o1[1], o1[2], o1[3],
                                 Phi[mt][kk][0], Phi[mt][kk][1], Phi[mt][kk][2], Phi[mt][kk][3],
                                 l2, l3);
                    }
                }
            }
        }
        __syncthreads();
    }

    #pragma unroll
    for (int mt = 0; mt < 2; mt++) {
        float invA = (lrow[mt][0] > 0.0f) ? (1.0f / lrow[mt][0]) : 0.0f;
        float invB = (lrow[mt][1] > 0.0f) ? (1.0f / lrow[mt][1]) : 0.0f;
        int rA = q0 + mBase + mt * 16 + gid;
        int rB = rA + 8;
        #pragma unroll
        for (int dj = 0; dj < 8; dj++) {
            int col = h * 64 + dj * 8 + tig * 2;
            float v0 = O[mt][dj][0] * invA, v1 = O[mt][dj][1] * invA;
            float v2 = O[mt][dj][2] * invB, v3 = O[mt][dj][3] * invB;
            size_t iA = ((size_t)rA * DIM + col) >> 1;
            size_t iB = ((size_t)rB * DIM + col) >> 1;
            __nv_bfloat162 hA = __floats2bfloat162_rn(v0, v1);
            __nv_bfloat162 hB = __floats2bfloat162_rn(v2, v3);
            ((uint32_t*)oh)[iA] = *(uint32_t*)&hA;
            ((uint32_t*)oh)[iB] = *(uint32_t*)&hB;
            ((uint32_t*)ol)[iA] = pack_bf16x2(v0 - __bfloat162float(hA.x),
                                              v1 - __bfloat162float(hA.y));
            ((uint32_t*)ol)[iB] = pack_bf16x2(v2 - __bfloat162float(hB.x),
                                              v3 - __bfloat162float(hB.y));
        }
    }
}

// ---------------- classification heads (768 -> 512 relu -> nout) ------------
__global__ void head_kernel(const float* __restrict__ x, const float* __restrict__ W1,
                            const float* __restrict__ b1, const float* __restrict__ W2,
                            const float* __restrict__ b2, float* __restrict__ out, int nout) {
    __shared__ float xs[768];
    __shared__ float hsm[512];
    int t = threadIdx.x;
    for (int i = t; i < 768; i += 512) xs[i] = x[i];
    __syncthreads();
    float acc = b1[t];
    for (int kk = 0; kk < 768; kk++) acc += xs[kk] * W1[(size_t)kk * 512 + t];
    hsm[t] = fmaxf(acc, 0.0f);
    __syncthreads();
    if (t < nout) {
        float ov = b2[t];
        for (int kk = 0; kk < 512; kk++) ov += hsm[kk] * W2[(size_t)kk * nout + t];
        out[t] = ov;
    }
}

// ---------------- host launcher ---------------------------------------------
extern "C" void kernel_launch(void* const* d_in, const int* in_sizes, int n_in,
                              void* d_out, int out_size) {
    const int*   ids      = (const int*)d_in[0];
    const int*   mask     = (const int*)d_in[1];
    const float* emb_word = (const float*)d_in[2];
    const float* emb_pos  = (const float*)d_in[3];
    const float* emb_type = (const float*)d_in[4];
    const float* emb_g    = (const float*)d_in[5];
    const float* emb_b    = (const float*)d_in[6];
    const float* Wq = (const float*)d_in[7];
    const float* bq = (const float*)d_in[8];
    const float* Wk = (const float*)d_in[9];
    const float* bk = (const float*)d_in[10];
    const float* Wv = (const float*)d_in[11];
    const float* bv = (const float*)d_in[12];
    const float* Wo = (const float*)d_in[13];
    const float* bo = (const float*)d_in[14];
    const float* ln1g = (const float*)d_in[15];
    const float* ln1b = (const float*)d_in[16];
    const float* W1 = (const float*)d_in[17];
    const float* b1 = (const float*)d_in[18];
    const float* W2 = (const float*)d_in[19];
    const float* b2 = (const float*)d_in[20];
    const float* ln2g = (const float*)d_in[21];
    const float* ln2b = (const float*)d_in[22];
    const float* cW1 = (const float*)d_in[23];
    const float* cb1 = (const float*)d_in[24];
    const float* cW2 = (const float*)d_in[25];
    const float* cb2 = (const float*)d_in[26];
    const float* dW1 = (const float*)d_in[27];
    const float* db1 = (const float*)d_in[28];
    const float* dW2 = (const float*)d_in[29];
    const float* db2 = (const float*)d_in[30];
    float* out = (float*)d_out;

    float *x, *qkv, *t, *bcat;
    int* pos;
    __nv_bfloat16 *xh, *xl, *ah, *al, *hh, *hl;
    __nv_bfloat16 *wqh, *wql, *w1h, *w1l, *w2h, *w2l, *woh, *wol;
    cudaGetSymbolAddress((void**)&x, g_x);
    cudaGetSymbolAddress((void**)&qkv, g_qkv);
    cudaGetSymbolAddress((void**)&t, g_t);
    cudaGetSymbolAddress((void**)&bcat, g_bcat);
    cudaGetSymbolAddress((void**)&pos, g_pos);
    cudaGetSymbolAddress((void**)&xh, g_xh);
    cudaGetSymbolAddress((void**)&xl, g_xl);
    cudaGetSymbolAddress((void**)&ah, g_ah);
    cudaGetSymbolAddress((void**)&al, g_al);
    cudaGetSymbolAddress((void**)&hh, g_hh);
    cudaGetSymbolAddress((void**)&hl, g_hl);
    cudaGetSymbolAddress((void**)&wqh, g_wqh);
    cudaGetSymbolAddress((void**)&wql, g_wql);
    cudaGetSymbolAddress((void**)&w1h, g_w1h);
    cudaGetSymbolAddress((void**)&w1l, g_w1l);
    cudaGetSymbolAddress((void**)&w2h, g_w2h);
    cudaGetSymbolAddress((void**)&w2l, g_w2l);
    cudaGetSymbolAddress((void**)&woh, g_woh);
    cudaGetSymbolAddress((void**)&wol, g_wol);

    const int SM128 = 2 * (2 * 128 * 64 + 16384);   // 65536
    const int SM64  = 2 * (2 * 64 * 64 + 16384);    // 49152
    cudaFuncSetAttribute(tgemm_kernel<128, 0>, cudaFuncAttributeMaxDynamicSharedMemorySize, SM128);
    cudaFuncSetAttribute(tgemm_kernel<128, 2>, cudaFuncAttributeMaxDynamicSharedMemorySize, SM128);
    cudaFuncSetAttribute(tgemm_kernel<64, 0>, cudaFuncAttributeMaxDynamicSharedMemorySize, SM64);
    cudaFuncSetAttribute(attn_mma_kernel, cudaFuncAttributeMaxDynamicSharedMemorySize, ATT_SMEM);

    pos_kernel<<<1, 1024>>>(mask, pos);
    embed_ln_kernel<<<SEQ, 256>>>(ids, pos, emb_word, emb_pos, emb_type, emb_g, emb_b, x, xh, xl);

    dim3 gqkv(3 * DIM / 128, SEQ / 128);   // (18, 32)
    dim3 go(DIM / 128, SEQ / 64);          // (6, 64) BM=64
    dim3 gff1(FFD / 128, SEQ / 128);       // (24, 32)
    dim3 gff2(DIM / 128, SEQ / 64);        // (6, 64) BM=64
    dim3 gattn(SEQ / 128, NH);
    int cgrid = (DIM * DIM / 4 + 255) / 256;

    for (int i = 0; i < NL; i++) {
        const float* wq = Wq + (size_t)i * DIM * DIM;
        const float* wk = Wk + (size_t)i * DIM * DIM;
        const float* wv = Wv + (size_t)i * DIM * DIM;
        const float* wo = Wo + (size_t)i * DIM * DIM;
        const float* w1 = W1 + (size_t)i * DIM * FFD;
        const float* w2 = W2 + (size_t)i * FFD * DIM;

        concat_qkv_kernel<<<cgrid, 256>>>(wq, wk, wv, bq + i * DIM, bk + i * DIM, bv + i * DIM,
                                          wqh, wql, bcat);
        split_kernel<<<(DIM * FFD / 4 + 255) / 256, 256>>>(w1, w1h, w1l, DIM * FFD / 4);
        split_kernel<<<(FFD * DIM / 4 + 255) / 256, 256>>>(w2, w2h, w2l, FFD * DIM / 4);
        split_kernel<<<(DIM * DIM / 4 + 255) / 256, 256>>>(wo, woh, wol, DIM * DIM / 4);

        tgemm_kernel<128, 0><<<gqkv, 256, SM128>>>(xh, xl, wqh, wql, bcat, qkv, nullptr, nullptr,
                                                   SEQ, 3 * DIM, DIM);
        attn_mma_kernel<<<gattn, 128, ATT_SMEM>>>(qkv, mask, ah, al);
        tgemm_kernel<64, 0><<<go, 256, SM64>>>(ah, al, woh, wol, bo + i * DIM, t, nullptr, nullptr,
                                               SEQ, DIM, DIM);
        lnres_kernel<<<SEQ, 256>>>(x, t, ln1g + i * DIM, ln1b + i * DIM, xh, xl);
        tgemm_kernel<128, 2><<<gff1, 256, SM128>>>(xh, xl, w1h, w1l, b1 + i * FFD, nullptr,
                                                   hh, hl, SEQ, FFD, DIM);
        tgemm_kernel<64, 0><<<gff2, 256, SM64>>>(hh, hl, w2h, w2l, b2 + i * DIM, t,
                                                 nullptr, nullptr, SEQ, DIM, FFD);
        lnres_kernel<<<SEQ, 256>>>(x, t, ln2g + i * DIM, ln2b + i * DIM, xh, xl);
    }

    head_kernel<<<1, 512>>>(x, cW1, cb1, cW2, cb2, out, 5);
    head_kernel<<<1, 512>>>(x, dW1, db1, dW2, db2, out + 5, 10);
}